// round 1
// baseline (speedup 1.0000x reference)
#include <cuda_runtime.h>
#include <math.h>
#include <stdint.h>

#define T_TOK 8192
#define DIM   768
#define FF    3072
#define NE    8
#define CAP   2560
#define MAXR  5120   // 2*CAP, max gathered rows per expert

// ---------------- static device scratch (no allocations allowed) ----------------
__device__ float g_H[(size_t)NE * MAXR * FF];   // gated-hidden per gathered row
__device__ float g_Y[(size_t)NE * MAXR * DIM];  // expert output per gathered row
__device__ int   g_tok[NE * MAXR];              // gathered token lists
__device__ int   g_topk[T_TOK * 2];
__device__ float g_topp[T_TOK * 2];             // normalized top-2 probs
__device__ int   g_rowidx[T_TOK * 2];           // gathered-row index per (t, k)
__device__ float g_wk[T_TOK * 2];               // kept weight per (t, k) (0 if dropped)
__device__ int   g_cnt[NE];                     // kept rows per expert
__device__ int   g_cnta[NE];                    // assignment counts (pre-capacity, for f)
__device__ float g_psum[NE];                    // sum of router probs per expert (for P)
__device__ float g_zsum;                        // sum of lse^2

// ---------------- helpers ----------------
__device__ __forceinline__ uint32_t f2tf(float f) {
    uint32_t r;
    asm("cvt.rna.tf32.f32 %0, %1;" : "=r"(r) : "f"(f));
    return r;
}

#define MMA_TF32(D, A, B0, B1)                                                   \
    asm volatile(                                                                \
        "mma.sync.aligned.m16n8k8.row.col.f32.tf32.tf32.f32 "                    \
        "{%0,%1,%2,%3}, {%4,%5,%6,%7}, {%8,%9}, {%0,%1,%2,%3};\n"                \
        : "+f"((D)[0]), "+f"((D)[1]), "+f"((D)[2]), "+f"((D)[3])                 \
        : "r"((A)[0]), "r"((A)[1]), "r"((A)[2]), "r"((A)[3]), "r"(B0), "r"(B1))

// ---------------- init: zero aux accumulators (re-run every graph replay) ----------------
__global__ void init_kernel() {
    int tid = threadIdx.x;
    if (tid < NE) { g_psum[tid] = 0.f; g_cnta[tid] = 0; }
    if (tid == 0) g_zsum = 0.f;
}

// ---------------- router: logits (fp32 exact), softmax, top-2, aux partials ----------------
__global__ void router_kernel(const float* __restrict__ x, const float* __restrict__ wg) {
    __shared__ float sg[NE * DIM];
    __shared__ float shp[NE];
    __shared__ int   shc[NE];
    __shared__ float shz;
    int tid = threadIdx.x;
    for (int i = tid; i < NE * DIM; i += 256) sg[i] = wg[i];
    if (tid < NE) { shp[tid] = 0.f; shc[tid] = 0; }
    if (tid == 0) shz = 0.f;
    __syncthreads();

    int w = tid >> 5, lane = tid & 31;
    int t = blockIdx.x * 8 + w;
    const float* xt = x + (size_t)t * DIM;
    float acc[NE];
#pragma unroll
    for (int e = 0; e < NE; e++) acc[e] = 0.f;
    for (int j = lane; j < DIM; j += 32) {
        float xv = xt[j];
#pragma unroll
        for (int e = 0; e < NE; e++) acc[e] += xv * sg[e * DIM + j];
    }
#pragma unroll
    for (int o = 16; o > 0; o >>= 1) {
#pragma unroll
        for (int e = 0; e < NE; e++) acc[e] += __shfl_xor_sync(0xffffffffu, acc[e], o);
    }
    if (lane == 0) {
        float m = acc[0];
#pragma unroll
        for (int e = 1; e < NE; e++) m = fmaxf(m, acc[e]);
        float p[NE]; float s = 0.f;
#pragma unroll
        for (int e = 0; e < NE; e++) { p[e] = expf(acc[e] - m); s += p[e]; }
        float inv = 1.f / s;
#pragma unroll
        for (int e = 0; e < NE; e++) p[e] *= inv;
        float lse = m + logf(s);
        int i0 = 0; float b0 = p[0];
#pragma unroll
        for (int e = 1; e < NE; e++) if (p[e] > b0) { b0 = p[e]; i0 = e; }
        int i1 = -1; float b1 = -1.f;
#pragma unroll
        for (int e = 0; e < NE; e++) if (e != i0 && p[e] > b1) { b1 = p[e]; i1 = e; }
        float invs = 1.f / (b0 + b1);
        g_topk[t * 2] = i0; g_topk[t * 2 + 1] = i1;
        g_topp[t * 2] = b0 * invs; g_topp[t * 2 + 1] = b1 * invs;
#pragma unroll
        for (int e = 0; e < NE; e++) atomicAdd(&shp[e], p[e]);
        atomicAdd(&shc[i0], 1);
        atomicAdd(&shc[i1], 1);
        atomicAdd(&shz, lse * lse);
    }
    __syncthreads();
    if (tid < NE) { atomicAdd(&g_psum[tid], shp[tid]); atomicAdd(&g_cnta[tid], shc[tid]); }
    if (tid == 0) atomicAdd(&g_zsum, shz);
}

// ---------------- scan: per-expert deterministic rank/capacity + gather list build ----------------
__global__ void scan_kernel() {
    int e = blockIdx.x;
    int tid = threadIdx.x;
    __shared__ int s0[256], s1[256], ss[256];
    __shared__ int base0, base1, baseS;
    if (tid == 0) { base0 = 0; base1 = 0; baseS = 0; }
    __syncthreads();
    for (int b = 0; b < T_TOK; b += 256) {
        int t = b + tid;
        int i0 = g_topk[t * 2], i1 = g_topk[t * 2 + 1];
        int a0 = (i0 == e) ? 1 : 0;
        int a1 = (i1 == e) ? 1 : 0;
        s0[tid] = a0; s1[tid] = a1;
        __syncthreads();
        for (int o = 1; o < 256; o <<= 1) {
            int v0 = 0, v1 = 0;
            if (tid >= o) { v0 = s0[tid - o]; v1 = s1[tid - o]; }
            __syncthreads();
            s0[tid] += v0; s1[tid] += v1;
            __syncthreads();
        }
        int r0 = base0 + s0[tid] - a0;
        int r1 = base1 + s1[tid] - a1;
        int k0 = a0 && (r0 < CAP);
        int k1 = a1 && (r1 < CAP);
        int sel = (k0 || k1) ? 1 : 0;
        ss[tid] = sel;
        __syncthreads();
        for (int o = 1; o < 256; o <<= 1) {
            int v = 0;
            if (tid >= o) v = ss[tid - o];
            __syncthreads();
            ss[tid] += v;
            __syncthreads();
        }
        int pos = baseS + ss[tid] - sel;
        if (sel) g_tok[e * MAXR + pos] = t;
        if (a0) { g_wk[t * 2]     = k0 ? g_topp[t * 2]     : 0.f; g_rowidx[t * 2]     = k0 ? (e * MAXR + pos) : 0; }
        if (a1) { g_wk[t * 2 + 1] = k1 ? g_topp[t * 2 + 1] : 0.f; g_rowidx[t * 2 + 1] = k1 ? (e * MAXR + pos) : 0; }
        __syncthreads();
        if (tid == 255) { base0 += s0[255]; base1 += s1[255]; baseS += ss[255]; }
        __syncthreads();
    }
    if (tid == 0) g_cnt[e] = baseS;
}

// ---------------- GEMM config ----------------
#define BM 128
#define BN 64
#define BK 16
#define LDT 20   // padded smem row stride (floats) -> conflict-free fragment loads

// GEMM1: H[row, n] = silu(Xg @ Wg^T) * (Xg @ Wu^T), gathered rows, fused gate+up
__global__ __launch_bounds__(256) void gemm1_kernel(const float* __restrict__ x,
                                                    const float* __restrict__ wig,
                                                    const float* __restrict__ wiu) {
    int e = blockIdx.z;
    int cnt = g_cnt[e];
    int m0 = blockIdx.y * BM;
    if (m0 >= cnt) return;
    int n0 = blockIdx.x * BN;

    __shared__ __align__(16) uint32_t As[2][BM * LDT];
    __shared__ __align__(16) uint32_t Bg[2][BN * LDT];
    __shared__ __align__(16) uint32_t Bu[2][BN * LDT];
    __shared__ int stok[BM];

    int tid = threadIdx.x;
    if (tid < BM) {
        int r = m0 + tid;
        stok[tid] = (r < cnt) ? g_tok[e * MAXR + r] : 0;
    }
    __syncthreads();

    int q  = tid & 3;       // quad of 4 floats within BK=16
    int rA = tid >> 2;      // 0..63 (rows rA and 64+rA)
    int nB = tid >> 2;      // 0..63
    const float* bgp = wig + (size_t)e * FF * DIM + (size_t)(n0 + nB) * DIM + q * 4;
    const float* bup = wiu + (size_t)e * FF * DIM + (size_t)(n0 + nB) * DIM + q * 4;

    int lane = tid & 31, wid = tid >> 5;
    int gid = lane >> 2, tig = lane & 3;
    int wm = wid & 3, wn = wid >> 2;

    float ag[2][4][4], au[2][4][4];
#pragma unroll
    for (int i = 0; i < 2; i++)
#pragma unroll
        for (int j = 0; j < 4; j++)
#pragma unroll
            for (int c = 0; c < 4; c++) { ag[i][j][c] = 0.f; au[i][j][c] = 0.f; }

    float4 rA0, rA1, rBg, rBu;

#define G1_LDG(kk)                                                                   \
    do {                                                                             \
        rA0 = *(const float4*)(x + (size_t)stok[rA] * DIM + (kk) + q * 4);           \
        rA1 = *(const float4*)(x + (size_t)stok[64 + rA] * DIM + (kk) + q * 4);      \
        rBg = *(const float4*)(bgp + (kk));                                          \
        rBu = *(const float4*)(bup + (kk));                                          \
    } while (0)

#define G1_STS(buf)                                                                  \
    do {                                                                             \
        uint4 u_;                                                                    \
        u_.x = f2tf(rA0.x); u_.y = f2tf(rA0.y); u_.z = f2tf(rA0.z); u_.w = f2tf(rA0.w); \
        *(uint4*)&As[buf][rA * LDT + q * 4] = u_;                                    \
        u_.x = f2tf(rA1.x); u_.y = f2tf(rA1.y); u_.z = f2tf(rA1.z); u_.w = f2tf(rA1.w); \
        *(uint4*)&As[buf][(64 + rA) * LDT + q * 4] = u_;                             \
        u_.x = f2tf(rBg.x); u_.y = f2tf(rBg.y); u_.z = f2tf(rBg.z); u_.w = f2tf(rBg.w); \
        *(uint4*)&Bg[buf][nB * LDT + q * 4] = u_;                                    \
        u_.x = f2tf(rBu.x); u_.y = f2tf(rBu.y); u_.z = f2tf(rBu.z); u_.w = f2tf(rBu.w); \
        *(uint4*)&Bu[buf][nB * LDT + q * 4] = u_;                                    \
    } while (0)

    const int NK = DIM / BK;  // 48
    G1_LDG(0);
    G1_STS(0);
    __syncthreads();
    for (int kt = 0; kt < NK; kt++) {
        int cur = kt & 1;
        if (kt + 1 < NK) G1_LDG((kt + 1) * BK);
        const uint32_t* A  = As[cur];
        const uint32_t* BGp = Bg[cur];
        const uint32_t* BUp = Bu[cur];
#pragma unroll
        for (int km = 0; km < 2; km++) {
            int kb = km * 8;
            uint32_t a[2][4];
#pragma unroll
            for (int im = 0; im < 2; im++) {
                int r = wm * 32 + im * 16 + gid;
                a[im][0] = A[r * LDT + kb + tig];
                a[im][1] = A[(r + 8) * LDT + kb + tig];
                a[im][2] = A[r * LDT + kb + tig + 4];
                a[im][3] = A[(r + 8) * LDT + kb + tig + 4];
            }
#pragma unroll
            for (int jn = 0; jn < 4; jn++) {
                int n = wn * 32 + jn * 8 + gid;
                uint32_t g0 = BGp[n * LDT + kb + tig], g1 = BGp[n * LDT + kb + tig + 4];
                uint32_t u0 = BUp[n * LDT + kb + tig], u1 = BUp[n * LDT + kb + tig + 4];
#pragma unroll
                for (int im = 0; im < 2; im++) {
                    MMA_TF32(ag[im][jn], a[im], g0, g1);
                    MMA_TF32(au[im][jn], a[im], u0, u1);
                }
            }
        }
        if (kt + 1 < NK) { G1_STS(cur ^ 1); __syncthreads(); }
    }

    // epilogue: h = silu(g) * u, write fp32 H
#pragma unroll
    for (int im = 0; im < 2; im++) {
#pragma unroll
        for (int jn = 0; jn < 4; jn++) {
            int rl  = wm * 32 + im * 16 + gid;
            int col = n0 + wn * 32 + jn * 8 + tig * 2;
            size_t b0i = (size_t)(e * MAXR + m0 + rl) * FF + col;
            size_t b1i = (size_t)(e * MAXR + m0 + rl + 8) * FF + col;
            float2 h0, h1;
            {
                float g = ag[im][jn][0], uu = au[im][jn][0];
                h0.x = g / (1.f + expf(-g)) * uu;
                g = ag[im][jn][1]; uu = au[im][jn][1];
                h0.y = g / (1.f + expf(-g)) * uu;
                g = ag[im][jn][2]; uu = au[im][jn][2];
                h1.x = g / (1.f + expf(-g)) * uu;
                g = ag[im][jn][3]; uu = au[im][jn][3];
                h1.y = g / (1.f + expf(-g)) * uu;
            }
            *(float2*)&g_H[b0i] = h0;
            *(float2*)&g_H[b1i] = h1;
        }
    }
}

// GEMM2: Y[row, n] = H[row, :] @ Wo[e]^T
__global__ __launch_bounds__(256) void gemm2_kernel(const float* __restrict__ wo) {
    int e = blockIdx.z;
    int cnt = g_cnt[e];
    int m0 = blockIdx.y * BM;
    if (m0 >= cnt) return;
    int n0 = blockIdx.x * BN;

    __shared__ __align__(16) uint32_t As[2][BM * LDT];
    __shared__ __align__(16) uint32_t Bs[2][BN * LDT];

    int tid = threadIdx.x;
    int q  = tid & 3;
    int rA = tid >> 2;
    int nB = tid >> 2;
    const float* ap0 = g_H + (size_t)(e * MAXR + m0 + rA) * FF + q * 4;
    const float* ap1 = g_H + (size_t)(e * MAXR + m0 + 64 + rA) * FF + q * 4;
    const float* bp  = wo + (size_t)e * DIM * FF + (size_t)(n0 + nB) * FF + q * 4;

    int lane = tid & 31, wid = tid >> 5;
    int gid = lane >> 2, tig = lane & 3;
    int wm = wid & 3, wn = wid >> 2;

    float acc[2][4][4];
#pragma unroll
    for (int i = 0; i < 2; i++)
#pragma unroll
        for (int j = 0; j < 4; j++)
#pragma unroll
            for (int c = 0; c < 4; c++) acc[i][j][c] = 0.f;

    float4 rA0, rA1, rB;

#define G2_LDG(kk)                                            \
    do {                                                      \
        rA0 = *(const float4*)(ap0 + (kk));                   \
        rA1 = *(const float4*)(ap1 + (kk));                   \
        rB  = *(const float4*)(bp + (kk));                    \
    } while (0)

#define G2_STS(buf)                                                                  \
    do {                                                                             \
        uint4 u_;                                                                    \
        u_.x = f2tf(rA0.x); u_.y = f2tf(rA0.y); u_.z = f2tf(rA0.z); u_.w = f2tf(rA0.w); \
        *(uint4*)&As[buf][rA * LDT + q * 4] = u_;                                    \
        u_.x = f2tf(rA1.x); u_.y = f2tf(rA1.y); u_.z = f2tf(rA1.z); u_.w = f2tf(rA1.w); \
        *(uint4*)&As[buf][(64 + rA) * LDT + q * 4] = u_;                             \
        u_.x = f2tf(rB.x); u_.y = f2tf(rB.y); u_.z = f2tf(rB.z); u_.w = f2tf(rB.w);  \
        *(uint4*)&Bs[buf][nB * LDT + q * 4] = u_;                                    \
    } while (0)

    const int NK = FF / BK;  // 192
    G2_LDG(0);
    G2_STS(0);
    __syncthreads();
    for (int kt = 0; kt < NK; kt++) {
        int cur = kt & 1;
        if (kt + 1 < NK) G2_LDG((kt + 1) * BK);
        const uint32_t* A = As[cur];
        const uint32_t* B = Bs[cur];
#pragma unroll
        for (int km = 0; km < 2; km++) {
            int kb = km * 8;
            uint32_t a[2][4];
#pragma unroll
            for (int im = 0; im < 2; im++) {
                int r = wm * 32 + im * 16 + gid;
                a[im][0] = A[r * LDT + kb + tig];
                a[im][1] = A[(r + 8) * LDT + kb + tig];
                a[im][2] = A[r * LDT + kb + tig + 4];
                a[im][3] = A[(r + 8) * LDT + kb + tig + 4];
            }
#pragma unroll
            for (int jn = 0; jn < 4; jn++) {
                int n = wn * 32 + jn * 8 + gid;
                uint32_t b0 = B[n * LDT + kb + tig], b1 = B[n * LDT + kb + tig + 4];
#pragma unroll
                for (int im = 0; im < 2; im++) MMA_TF32(acc[im][jn], a[im], b0, b1);
            }
        }
        if (kt + 1 < NK) { G2_STS(cur ^ 1); __syncthreads(); }
    }

#pragma unroll
    for (int im = 0; im < 2; im++) {
#pragma unroll
        for (int jn = 0; jn < 4; jn++) {
            int rl  = wm * 32 + im * 16 + gid;
            int col = n0 + wn * 32 + jn * 8 + tig * 2;
            size_t b0i = (size_t)(e * MAXR + m0 + rl) * DIM + col;
            size_t b1i = (size_t)(e * MAXR + m0 + rl + 8) * DIM + col;
            float2 y0 = make_float2(acc[im][jn][0], acc[im][jn][1]);
            float2 y1 = make_float2(acc[im][jn][2], acc[im][jn][3]);
            *(float2*)&g_Y[b0i] = y0;
            *(float2*)&g_Y[b1i] = y1;
        }
    }
}

// ---------------- combine: out[t] = sum_k w[t,k] * Y[row[t,k]] (no atomics, deterministic) ----------------
__global__ void combine_kernel(float* __restrict__ out) {
    int gi = blockIdx.x * 256 + threadIdx.x;  // float4 index, total T*D/4
    int t = gi / (DIM / 4);
    int c = (gi % (DIM / 4)) * 4;
    float w0 = g_wk[t * 2], w1 = g_wk[t * 2 + 1];
    float4 acc = make_float4(0.f, 0.f, 0.f, 0.f);
    if (w0 > 0.f) {
        const float4 y = *(const float4*)&g_Y[(size_t)g_rowidx[t * 2] * DIM + c];
        acc.x = w0 * y.x; acc.y = w0 * y.y; acc.z = w0 * y.z; acc.w = w0 * y.w;
    }
    if (w1 > 0.f) {
        const float4 y = *(const float4*)&g_Y[(size_t)g_rowidx[t * 2 + 1] * DIM + c];
        acc.x += w1 * y.x; acc.y += w1 * y.y; acc.z += w1 * y.z; acc.w += w1 * y.w;
    }
    *(float4*)(out + (size_t)gi * 4) = acc;
}

// ---------------- finalize: aux loss scalar ----------------
__global__ void finalize_kernel(float* __restrict__ out, int out_size) {
    if (threadIdx.x == 0 && out_size > T_TOK * DIM) {
        float lb = 0.f;
        for (int e = 0; e < NE; e++) {
            float f = (float)g_cnta[e] / (float)(T_TOK * 2);
            float P = g_psum[e] / (float)T_TOK;
            lb += f * P;
        }
        lb *= (float)NE;
        float z = g_zsum / (float)T_TOK;
        out[T_TOK * DIM] = 0.01f * lb + 0.001f * z;
    }
}

// ---------------- launch ----------------
extern "C" void kernel_launch(void* const* d_in, const int* in_sizes, int n_in,
                              void* d_out, int out_size) {
    (void)in_sizes; (void)n_in;
    const float* x   = (const float*)d_in[0];
    const float* wg  = (const float*)d_in[1];
    const float* wig = (const float*)d_in[2];
    const float* wiu = (const float*)d_in[3];
    const float* wo  = (const float*)d_in[4];
    float* out = (float*)d_out;

    init_kernel<<<1, 32>>>();
    router_kernel<<<T_TOK / 8, 256>>>(x, wg);
    scan_kernel<<<NE, 256>>>();
    gemm1_kernel<<<dim3(FF / BN, MAXR / BM, NE), 256>>>(x, wig, wiu);
    gemm2_kernel<<<dim3(DIM / BN, MAXR / BM, NE), 256>>>(wo);
    combine_kernel<<<(T_TOK * DIM / 4) / 256, 256>>>(out);
    finalize_kernel<<<1, 1>>>(out, out_size);
}